// round 4
// baseline (speedup 1.0000x reference)
#include <cuda_runtime.h>

// Circuit in linear probability space (one log at the end):
//   p_v = exp(l_v);  s = p1(1-p2) + (1-p1)p2;  t = p1*p2
//   out = log(p0*s + (1-p0)*t)
// Identical to the reference's nested logsumexp (slot-9's -1000 disjunct
// exp-underflows to exactly 0 there too).
__device__ __forceinline__ float circuit_eval(float l0, float l1, float l2) {
    float p0 = __expf(l0);
    float p1 = __expf(l1);
    float p2 = __expf(l2);

    float t  = p1 * p2;
    float a  = __fmaf_rn(-p1, p2, p1);    // p1*(1-p2)
    float b  = __fmaf_rn(-p1, p2, p2);    // (1-p1)*p2
    float s  = a + b;

    float q0 = 1.0f - p0;
    float x  = __fmaf_rn(p0, s, q0 * t);
    return __logf(x);
}

// Warp tile: 256 elements = 192 float4 in, 64 float4 out.
// 6 coalesced LDG.128 up front (MLP=6), staged through smem so each lane
// owns complete elements, then 2 coalesced STG.128.
static constexpr int WARPS_PER_BLOCK = 8;
static constexpr int THREADS = WARPS_PER_BLOCK * 32;

__global__ void __launch_bounds__(THREADS)
circuit_kernel(const float4* __restrict__ in, float4* __restrict__ out,
               int n_tiles) {
    __shared__ float4 tile[WARPS_PER_BLOCK][192];

    int warp = threadIdx.x >> 5;
    int lane = threadIdx.x & 31;
    int g = blockIdx.x * WARPS_PER_BLOCK + warp;
    if (g >= n_tiles) return;

    // 6 independent coalesced loads (each = contiguous 512B across the warp)
    const float4* pin = in + (size_t)g * 192;
    float4 v[6];
#pragma unroll
    for (int k = 0; k < 6; k++) v[k] = pin[k * 32 + lane];

#pragma unroll
    for (int k = 0; k < 6; k++) tile[warp][k * 32 + lane] = v[k];
    __syncwarp();

    // First 128 elements: lane owns float4s [3*lane .. 3*lane+2]
    // (48B lane stride -> banks {12t..12t+3 mod 32}, conflict-free).
    float4 r0, r1;
    {
        float4 a = tile[warp][3 * lane + 0];
        float4 b = tile[warp][3 * lane + 1];
        float4 c = tile[warp][3 * lane + 2];
        r0.x = circuit_eval(a.x, a.y, a.z);
        r0.y = circuit_eval(a.w, b.x, b.y);
        r0.z = circuit_eval(b.z, b.w, c.x);
        r0.w = circuit_eval(c.y, c.z, c.w);
    }
    // Second 128 elements: same pattern shifted by 96 float4 (0 mod 32 banks).
    {
        float4 a = tile[warp][96 + 3 * lane + 0];
        float4 b = tile[warp][96 + 3 * lane + 1];
        float4 c = tile[warp][96 + 3 * lane + 2];
        r1.x = circuit_eval(a.x, a.y, a.z);
        r1.y = circuit_eval(a.w, b.x, b.y);
        r1.z = circuit_eval(b.z, b.w, c.x);
        r1.w = circuit_eval(c.y, c.z, c.w);
    }

    // 2 coalesced stores (contiguous 512B each).
    float4* pout = out + (size_t)g * 64;
    pout[lane]      = r0;
    pout[32 + lane] = r1;
}

// Tail for elements beyond the last full 256-element warp tile
// (not hit for B=4194304).
__global__ void circuit_tail_kernel(const float* __restrict__ in,
                                    float* __restrict__ out,
                                    int start, int n) {
    int i = start + blockIdx.x * blockDim.x + threadIdx.x;
    if (i >= n) return;
    out[i] = circuit_eval(in[3 * i + 0], in[3 * i + 1], in[3 * i + 2]);
}

extern "C" void kernel_launch(void* const* d_in, const int* in_sizes, int n_in,
                              void* d_out, int out_size) {
    const float* log_probs = (const float*)d_in[0];
    float* out = (float*)d_out;

    int B = out_size;                 // output is (1, B) floats
    int n_tiles = B / 256;            // 256 elements per warp tile

    if (n_tiles > 0) {
        int blocks = (n_tiles + WARPS_PER_BLOCK - 1) / WARPS_PER_BLOCK;
        circuit_kernel<<<blocks, THREADS>>>(
            (const float4*)log_probs, (float4*)out, n_tiles);
    }
    int done = n_tiles * 256;
    if (done < B) {
        int rem = B - done;
        circuit_tail_kernel<<<(rem + 255) / 256, 256>>>(log_probs, out, done, B);
    }
}

// round 5
// speedup vs baseline: 1.0025x; 1.0025x over previous
#include <cuda_runtime.h>

// Circuit in linear probability space (one log at the end):
//   p_v = exp(l_v);  s = p1(1-p2) + (1-p1)p2;  t = p1*p2
//   out = log(p0*s + (1-p0)*t)
// Identical to the reference's nested logsumexp (slot-9's -1000 disjunct
// exp-underflows to exactly 0 there too).
__device__ __forceinline__ float circuit_eval(float l0, float l1, float l2) {
    float p0 = __expf(l0);
    float p1 = __expf(l1);
    float p2 = __expf(l2);

    float t  = p1 * p2;
    float a  = __fmaf_rn(-p1, p2, p1);    // p1*(1-p2)
    float b  = __fmaf_rn(-p1, p2, p2);    // (1-p1)*p2
    float s  = a + b;

    float q0 = 1.0f - p0;
    float x  = __fmaf_rn(p0, s, q0 * t);
    return __logf(x);
}

// Warp tile: 128 elements = 96 float4 in, 32 float4 out.
// Persistent warps, grid-stride over tiles, software pipeline:
// prefetch tile k+1's 3 coalesced LDG.128 before computing tile k
// (double-buffered smem transpose, conflict-free LDS.128).
static constexpr int WARPS_PER_BLOCK = 8;
static constexpr int THREADS = WARPS_PER_BLOCK * 32;

__global__ void
circuit_kernel(const float4* __restrict__ in, float4* __restrict__ out,
               int n_tiles) {
    __shared__ float4 tile[2][WARPS_PER_BLOCK][96];

    int warp = threadIdx.x >> 5;
    int lane = threadIdx.x & 31;
    int total_warps = gridDim.x * WARPS_PER_BLOCK;
    int g = blockIdx.x * WARPS_PER_BLOCK + warp;
    if (g >= n_tiles) return;

    // Prologue: load first tile (3 coalesced 512B loads).
    float4 v0, v1, v2;
    {
        const float4* p = in + (size_t)g * 96;
        v0 = p[lane];
        v1 = p[32 + lane];
        v2 = p[64 + lane];
    }

    int buf = 0;
    while (true) {
        // Stage current tile (STS.128, contiguous -> conflict-free).
        tile[buf][warp][lane]      = v0;
        tile[buf][warp][32 + lane] = v1;
        tile[buf][warp][64 + lane] = v2;

        // Prefetch next tile BEFORE computing current: its DRAM latency
        // overlaps the LDS+compute+STG below (and the next wait).
        int gn = g + total_warps;
        bool more = gn < n_tiles;
        if (more) {
            const float4* p = in + (size_t)gn * 96;
            v0 = p[lane];
            v1 = p[32 + lane];
            v2 = p[64 + lane];
        }

        __syncwarp();   // STS visible; also orders buf reuse (2-deep)

        // Each lane reads 3 consecutive float4 = 4 complete elements.
        // 48B lane stride -> banks {12t..12t+3 mod 32}: conflict-free.
        float4 a = tile[buf][warp][3 * lane + 0];
        float4 b = tile[buf][warp][3 * lane + 1];
        float4 c = tile[buf][warp][3 * lane + 2];

        float4 r;
        r.x = circuit_eval(a.x, a.y, a.z);
        r.y = circuit_eval(a.w, b.x, b.y);
        r.z = circuit_eval(b.z, b.w, c.x);
        r.w = circuit_eval(c.y, c.z, c.w);

        // Coalesced store (contiguous 512B across the warp).
        out[(size_t)g * 32 + lane] = r;

        if (!more) break;
        g = gn;
        buf ^= 1;
    }
}

// Tail for elements beyond the last full 128-element warp tile
// (not hit for B=4194304).
__global__ void circuit_tail_kernel(const float* __restrict__ in,
                                    float* __restrict__ out,
                                    int start, int n) {
    int i = start + blockIdx.x * blockDim.x + threadIdx.x;
    if (i >= n) return;
    out[i] = circuit_eval(in[3 * i + 0], in[3 * i + 1], in[3 * i + 2]);
}

extern "C" void kernel_launch(void* const* d_in, const int* in_sizes, int n_in,
                              void* d_out, int out_size) {
    const float* log_probs = (const float*)d_in[0];
    float* out = (float*)d_out;

    int B = out_size;                 // output is (1, B) floats
    int n_tiles = B / 128;            // 128 elements per warp tile

    if (n_tiles > 0) {
        // One full wave of persistent CTAs (148 SMs x 8 CTAs at 256 thr),
        // capped by available tiles.
        int blocks = 1184;
        int max_blocks = (n_tiles + WARPS_PER_BLOCK - 1) / WARPS_PER_BLOCK;
        if (blocks > max_blocks) blocks = max_blocks;
        circuit_kernel<<<blocks, THREADS>>>(
            (const float4*)log_probs, (float4*)out, n_tiles);
    }
    int done = n_tiles * 128;
    if (done < B) {
        int rem = B - done;
        circuit_tail_kernel<<<(rem + 255) / 256, 256>>>(log_probs, out, done, B);
    }
}